// round 3
// baseline (speedup 1.0000x reference)
#include <cuda_runtime.h>
#include <math.h>

#define Nn 50000
#define Ee 1600000
#define Fdim 512
#define Hdim 128
#define Cdim 40
#define EPSv 0.3f

// ---------------- scratch (static device globals; no allocations) ----------
__device__ __align__(16) float g_raw[(size_t)Nn * Hdim];
__device__ __align__(16) float g_hA[(size_t)Nn * Hdim];
__device__ __align__(16) float g_hB[(size_t)Nn * Hdim];
__device__ float g_al[Nn];
__device__ float g_ar[Nn];
__device__ float g_dis[Nn];
__device__ int   g_cnt[Nn];
__device__ int   g_rowptr[Nn + 1];
__device__ int   g_cursor[Nn];
__device__ __align__(16) int2 g_edge[Ee];   // {src, bitcast(norm)} grouped by dst
__device__ int   g_bsum[256];
__device__ int   g_mode;                    // 0=int32, 1=int64, 2=float32

__device__ __forceinline__ float* buf_sel(int s) {
    return s == 0 ? g_raw : (s == 1 ? g_hA : g_hB);
}

// ---------------- edge dtype detection -------------------------------------
__global__ void k_detect(const unsigned* __restrict__ w) {
    if (threadIdx.x != 0 || blockIdx.x != 0) return;
    int odd_zero = 0, big_exp = 0;
#pragma unroll
    for (int i = 0; i < 64; i++) {
        unsigned lo = w[2 * i];
        unsigned hi = w[2 * i + 1];
        if (hi == 0u) odd_zero++;
        if (lo >= 0x46000000u) big_exp++;   // float bit pattern >= 8192.0f
    }
    int m;
    if (odd_zero >= 60) m = 1;              // int64: high words are zero
    else if (big_exp >= 20) m = 2;          // float32: large exponents dominate
    else m = 0;                             // int32: raw ids < 50000
    g_mode = m;
}

__device__ __forceinline__ int read_idx(const void* ei, size_t pos, int mode) {
    if (mode == 1) return (int)((const long long*)ei)[pos];
    if (mode == 2) return (int)((const float*)ei)[pos];
    return ((const int*)ei)[pos];
}

// ---------------- CSR build --------------------------------------------------
__global__ void k_zero_cnt(int n) {
    int i = blockIdx.x * blockDim.x + threadIdx.x;
    if (i < n) g_cnt[i] = 0;
}

__global__ void k_hist(const void* __restrict__ ei, int e_total) {
    int e = blockIdx.x * blockDim.x + threadIdx.x;
    if (e < e_total) {
        int mode = g_mode;
        int dst = read_idx(ei, (size_t)Ee + e, mode);
        if ((unsigned)dst < (unsigned)Nn) atomicAdd(&g_cnt[dst], 1);
    }
}

__global__ void k_dis(int n) {
    int i = blockIdx.x * blockDim.x + threadIdx.x;
    if (i < n) g_dis[i] = rsqrtf((float)(g_cnt[i] + 1));  // +1 self loop
}

__global__ void k_scan1(int n) {
    __shared__ int s[256];
    int tid = threadIdx.x;
    int i = blockIdx.x * 256 + tid;
    int v = (i < n) ? g_cnt[i] : 0;
    s[tid] = v;
    __syncthreads();
#pragma unroll
    for (int off = 1; off < 256; off <<= 1) {
        int t = (tid >= off) ? s[tid - off] : 0;
        __syncthreads();
        s[tid] += t;
        __syncthreads();
    }
    if (i < n) g_rowptr[i] = s[tid] - v;
    if (tid == 255) g_bsum[blockIdx.x] = s[255];
}

__global__ void k_scan2(int nblocks) {
    __shared__ int s[256];
    int tid = threadIdx.x;
    int v = (tid < nblocks) ? g_bsum[tid] : 0;
    s[tid] = v;
    __syncthreads();
#pragma unroll
    for (int off = 1; off < 256; off <<= 1) {
        int t = (tid >= off) ? s[tid - off] : 0;
        __syncthreads();
        s[tid] += t;
        __syncthreads();
    }
    g_bsum[tid] = s[tid] - v;
}

__global__ void k_scan3(int n) {
    int i = blockIdx.x * blockDim.x + threadIdx.x;
    if (i < n) {
        int rp = g_rowptr[i] + g_bsum[blockIdx.x];
        g_rowptr[i] = rp;
        g_cursor[i] = rp;
    }
    if (i == 0) g_rowptr[Nn] = Ee;
}

__global__ void k_fill(const void* __restrict__ ei, int e_total) {
    int e = blockIdx.x * blockDim.x + threadIdx.x;
    if (e < e_total) {
        int mode = g_mode;
        int src = read_idx(ei, (size_t)e, mode);
        int dst = read_idx(ei, (size_t)Ee + e, mode);
        if ((unsigned)src < (unsigned)Nn && (unsigned)dst < (unsigned)Nn) {
            int pos = atomicAdd(&g_cursor[dst], 1);
            float nrm = g_dis[src] * g_dis[dst];
            g_edge[pos] = make_int2(src, __float_as_int(nrm));
        }
    }
}

// ---------------- GEMM1: g_raw = relu(x @ W1^T + b1) ------------------------
__global__ void __launch_bounds__(256) k_gemm1(const float* __restrict__ x,
                                               const float* __restrict__ W1,
                                               const float* __restrict__ b1) {
    __shared__ float xs[32][72];
    __shared__ float ws[32][132];
    int tid = threadIdx.x;
    int rowBlk = blockIdx.x * 64;

    float acc[8][4];
#pragma unroll
    for (int u = 0; u < 8; u++)
#pragma unroll
        for (int v = 0; v < 4; v++) acc[u][v] = 0.f;

    for (int k0 = 0; k0 < Fdim; k0 += 32) {
#pragma unroll
        for (int u = 0; u < 2; u++) {
            int idx = tid + u * 256;
            int r = idx >> 3, c4 = idx & 7;
            float4 v = make_float4(0.f, 0.f, 0.f, 0.f);
            int gr = rowBlk + r;
            if (gr < Nn) v = *(const float4*)(x + (size_t)gr * Fdim + k0 + c4 * 4);
            xs[c4 * 4 + 0][r] = v.x; xs[c4 * 4 + 1][r] = v.y;
            xs[c4 * 4 + 2][r] = v.z; xs[c4 * 4 + 3][r] = v.w;
        }
#pragma unroll
        for (int u = 0; u < 4; u++) {
            int idx = tid + u * 256;
            int j = idx >> 3, c4 = idx & 7;
            float4 v = *(const float4*)(W1 + (size_t)j * Fdim + k0 + c4 * 4);
            ws[c4 * 4 + 0][j] = v.x; ws[c4 * 4 + 1][j] = v.y;
            ws[c4 * 4 + 2][j] = v.z; ws[c4 * 4 + 3][j] = v.w;
        }
        __syncthreads();

        int r0 = (tid >> 5) * 8;
        int c0 = (tid & 31) * 4;
#pragma unroll
        for (int kk = 0; kk < 32; kk++) {
            float4 wv = *(const float4*)&ws[kk][c0];
            float4 xa = *(const float4*)&xs[kk][r0];
            float4 xb = *(const float4*)&xs[kk][r0 + 4];
            float xv[8] = {xa.x, xa.y, xa.z, xa.w, xb.x, xb.y, xb.z, xb.w};
#pragma unroll
            for (int u = 0; u < 8; u++) {
                acc[u][0] = fmaf(xv[u], wv.x, acc[u][0]);
                acc[u][1] = fmaf(xv[u], wv.y, acc[u][1]);
                acc[u][2] = fmaf(xv[u], wv.z, acc[u][2]);
                acc[u][3] = fmaf(xv[u], wv.w, acc[u][3]);
            }
        }
        __syncthreads();
    }

    int r0 = (tid >> 5) * 8;
    int c0 = (tid & 31) * 4;
    float bb0 = b1[c0], bb1 = b1[c0 + 1], bb2 = b1[c0 + 2], bb3 = b1[c0 + 3];
#pragma unroll
    for (int u = 0; u < 8; u++) {
        int gr = rowBlk + r0 + u;
        if (gr < Nn) {
            float4 o;
            o.x = fmaxf(acc[u][0] + bb0, 0.f);
            o.y = fmaxf(acc[u][1] + bb1, 0.f);
            o.z = fmaxf(acc[u][2] + bb2, 0.f);
            o.w = fmaxf(acc[u][3] + bb3, 0.f);
            *(float4*)(g_raw + (size_t)gr * Hdim + c0) = o;
        }
    }
}

// ---------------- per-layer attention scalars: al, ar ----------------------
__global__ void k_att(int hin_sel, const float* __restrict__ attl,
                      const float* __restrict__ attr) {
    int gw = (blockIdx.x * blockDim.x + threadIdx.x) >> 5;
    int lane = threadIdx.x & 31;
    if (gw >= Nn) return;
    const float4* h4 = (const float4*)(buf_sel(hin_sel) + (size_t)gw * Hdim);
    float4 hv = h4[lane];
    float4 lv = ((const float4*)attl)[lane];
    float4 rv = ((const float4*)attr)[lane];
    float a = hv.x * lv.x + hv.y * lv.y + hv.z * lv.z + hv.w * lv.w;
    float b = hv.x * rv.x + hv.y * rv.y + hv.z * rv.z + hv.w * rv.w;
#pragma unroll
    for (int o = 16; o; o >>= 1) {
        a += __shfl_down_sync(0xffffffffu, a, o);
        b += __shfl_down_sync(0xffffffffu, b, o);
    }
    if (lane == 0) { g_al[gw] = a; g_ar[gw] = b; }
}

// ---------------- aggregation: one warp per node, CSR gather ---------------
__global__ void k_agg(int hin_sel, int hout_sel) {
    int gw = (blockIdx.x * blockDim.x + threadIdx.x) >> 5;
    int lane = threadIdx.x & 31;
    if (gw >= Nn) return;
    const float4* hin4 = (const float4*)buf_sel(hin_sel);

    float4 acc = make_float4(0.f, 0.f, 0.f, 0.f);
    float ar_i = g_ar[gw];
    int start = g_rowptr[gw];
    int end = g_rowptr[gw + 1];

    for (int base = start; base < end; base += 32) {
        int e = base + lane;
        float coef = 0.f;
        int src = 0;
        if (e < end) {
            int2 ed = g_edge[e];
            src = ed.x;
            coef = tanhf(g_al[src] + ar_i) * __int_as_float(ed.y);
        }
        int m = min(32, end - base);
        for (int j = 0; j < m; j++) {
            int s = __shfl_sync(0xffffffffu, src, j);
            float c = __shfl_sync(0xffffffffu, coef, j);
            float4 hv = hin4[(size_t)s * 32 + lane];
            acc.x = fmaf(c, hv.x, acc.x);
            acc.y = fmaf(c, hv.y, acc.y);
            acc.z = fmaf(c, hv.z, acc.z);
            acc.w = fmaf(c, hv.w, acc.w);
        }
    }
    float d = g_dis[gw];
    float cs = tanhf(g_al[gw] + ar_i) * d * d;
    float4 hvi = hin4[(size_t)gw * 32 + lane];
    float4 rw = ((const float4*)g_raw)[(size_t)gw * 32 + lane];
    acc.x += cs * hvi.x + EPSv * rw.x;
    acc.y += cs * hvi.y + EPSv * rw.y;
    acc.z += cs * hvi.z + EPSv * rw.z;
    acc.w += cs * hvi.w + EPSv * rw.w;
    ((float4*)buf_sel(hout_sel))[(size_t)gw * 32 + lane] = acc;
}

// ---------------- output: logits + log_softmax ------------------------------
__global__ void k_out(int hin_sel, const float* __restrict__ W2,
                      const float* __restrict__ b2, float* __restrict__ out) {
    __shared__ float slog[8][40];
    int gw = (blockIdx.x * blockDim.x + threadIdx.x) >> 5;
    int lane = threadIdx.x & 31;
    int lw = threadIdx.x >> 5;
    if (gw >= Nn) return;
    const float4* h4 = (const float4*)(buf_sel(hin_sel) + (size_t)gw * Hdim);
    float4 hv = h4[lane];
#pragma unroll
    for (int c = 0; c < Cdim; c++) {
        float4 wv = *(const float4*)(W2 + (size_t)c * Hdim + lane * 4);
        float p = hv.x * wv.x + hv.y * wv.y + hv.z * wv.z + hv.w * wv.w;
        p += __shfl_down_sync(0xffffffffu, p, 16);
        p += __shfl_down_sync(0xffffffffu, p, 8);
        p += __shfl_down_sync(0xffffffffu, p, 4);
        p += __shfl_down_sync(0xffffffffu, p, 2);
        p += __shfl_down_sync(0xffffffffu, p, 1);
        if (lane == 0) slog[lw][c] = p + b2[c];
    }
    __syncwarp();
    float m = -1e30f;
    for (int c = lane; c < Cdim; c += 32) m = fmaxf(m, slog[lw][c]);
#pragma unroll
    for (int o = 16; o; o >>= 1) m = fmaxf(m, __shfl_xor_sync(0xffffffffu, m, o));
    float s = 0.f;
    for (int c = lane; c < Cdim; c += 32) s += expf(slog[lw][c] - m);
#pragma unroll
    for (int o = 16; o; o >>= 1) s += __shfl_xor_sync(0xffffffffu, s, o);
    float lse = m + logf(s);
    for (int c = lane; c < Cdim; c += 32)
        out[(size_t)gw * Cdim + c] = slog[lw][c] - lse;
}

// ---------------- launch -----------------------------------------------------
extern "C" void kernel_launch(void* const* d_in, const int* in_sizes, int n_in,
                              void* d_out, int out_size) {
    const float* x = (const float*)d_in[0];
    const void* ei = (const void*)d_in[1];
    const float* W1 = (const float*)d_in[2];
    const float* b1 = (const float*)d_in[3];
    const float* W2 = (const float*)d_in[4];
    const float* b2 = (const float*)d_in[5];
    const float* attl = (const float*)d_in[6];
    const float* attr = (const float*)d_in[7];
    float* out = (float*)d_out;

    const int NBn = (Nn + 255) / 256;        // 196
    const int NBe = (Ee + 255) / 256;        // 6250
    const int NBw = (Nn * 32 + 255) / 256;   // 6250 (warp per node)

    k_detect<<<1, 32>>>((const unsigned*)ei);
    k_zero_cnt<<<NBn, 256>>>(Nn);
    k_hist<<<NBe, 256>>>(ei, Ee);
    k_dis<<<NBn, 256>>>(Nn);
    k_scan1<<<NBn, 256>>>(Nn);
    k_scan2<<<1, 256>>>(NBn);
    k_scan3<<<NBn, 256>>>(Nn);
    k_fill<<<NBe, 256>>>(ei, Ee);

    k_gemm1<<<(Nn + 63) / 64, 256>>>(x, W1, b1);

    int sel_in = 0, sel_out = 1;
    for (int l = 0; l < 4; l++) {
        k_att<<<NBw, 256>>>(sel_in, attl + l * Hdim, attr + l * Hdim);
        k_agg<<<NBw, 256>>>(sel_in, sel_out);
        sel_in = sel_out;
        sel_out = (sel_in == 1) ? 2 : 1;
    }
    k_out<<<NBw, 256>>>(sel_in, W2, b2, out);
}

// round 4
// speedup vs baseline: 1.0250x; 1.0250x over previous
#include <cuda_runtime.h>
#include <math.h>

#define Nn 50000
#define Ee 1600000
#define Fdim 512
#define Hdim 128
#define Cdim 40
#define EPSv 0.3f

// ---------------- scratch (static device globals; no allocations) ----------
__device__ __align__(16) float g_raw[(size_t)Nn * Hdim];
__device__ __align__(16) float g_hA[(size_t)Nn * Hdim];
__device__ __align__(16) float g_hB[(size_t)Nn * Hdim];
__device__ float g_al[2][Nn];     // double-buffered attention scalars
__device__ float g_ar[2][Nn];
__device__ float g_dis[Nn];
__device__ int   g_cnt[Nn];
__device__ int   g_rowptr[Nn + 1];
__device__ int   g_cursor[Nn];
__device__ __align__(16) int2 g_edge[Ee];   // {src, bitcast(norm)} grouped by dst
__device__ int   g_bsum[256];
__device__ int   g_mode;                    // 0=int32, 1=int64, 2=float32

__device__ __forceinline__ float* buf_sel(int s) {
    return s == 0 ? g_raw : (s == 1 ? g_hA : g_hB);
}

// ---------------- f32x2 helpers (sm_103a packed FMA) ------------------------
__device__ __forceinline__ void ffma2(unsigned long long& d,
                                      unsigned long long a,
                                      unsigned long long b) {
    asm volatile("fma.rn.f32x2 %0, %1, %2, %0;" : "+l"(d) : "l"(a), "l"(b));
}
__device__ __forceinline__ unsigned long long dup2(float w) {
    unsigned long long r;
    asm("mov.b64 %0, {%1,%1};" : "=l"(r) : "f"(w));
    return r;
}
__device__ __forceinline__ float2 unpk(unsigned long long v) {
    float2 r;
    asm("mov.b64 {%0,%1}, %2;" : "=f"(r.x), "=f"(r.y) : "l"(v));
    return r;
}

// ---------------- edge dtype detection -------------------------------------
__global__ void k_detect(const unsigned* __restrict__ w) {
    if (threadIdx.x != 0 || blockIdx.x != 0) return;
    int odd_zero = 0, big_exp = 0;
#pragma unroll
    for (int i = 0; i < 64; i++) {
        unsigned lo = w[2 * i];
        unsigned hi = w[2 * i + 1];
        if (hi == 0u) odd_zero++;
        if (lo >= 0x46000000u) big_exp++;
    }
    int m;
    if (odd_zero >= 60) m = 1;
    else if (big_exp >= 20) m = 2;
    else m = 0;
    g_mode = m;
}

__device__ __forceinline__ int read_idx(const void* ei, size_t pos, int mode) {
    if (mode == 1) return (int)((const long long*)ei)[pos];
    if (mode == 2) return (int)((const float*)ei)[pos];
    return ((const int*)ei)[pos];
}

// ---------------- CSR build --------------------------------------------------
__global__ void k_zero_cnt(int n) {
    int i = blockIdx.x * blockDim.x + threadIdx.x;
    if (i < n) g_cnt[i] = 0;
}

__global__ void k_hist(const void* __restrict__ ei, int e_total) {
    int e = blockIdx.x * blockDim.x + threadIdx.x;
    if (e < e_total) {
        int dst = read_idx(ei, (size_t)Ee + e, g_mode);
        if ((unsigned)dst < (unsigned)Nn) atomicAdd(&g_cnt[dst], 1);
    }
}

__global__ void k_dis(int n) {
    int i = blockIdx.x * blockDim.x + threadIdx.x;
    if (i < n) g_dis[i] = rsqrtf((float)(g_cnt[i] + 1));
}

__global__ void k_scan1(int n) {
    __shared__ int s[256];
    int tid = threadIdx.x;
    int i = blockIdx.x * 256 + tid;
    int v = (i < n) ? g_cnt[i] : 0;
    s[tid] = v;
    __syncthreads();
#pragma unroll
    for (int off = 1; off < 256; off <<= 1) {
        int t = (tid >= off) ? s[tid - off] : 0;
        __syncthreads();
        s[tid] += t;
        __syncthreads();
    }
    if (i < n) g_rowptr[i] = s[tid] - v;
    if (tid == 255) g_bsum[blockIdx.x] = s[255];
}

__global__ void k_scan2(int nblocks) {
    __shared__ int s[256];
    int tid = threadIdx.x;
    int v = (tid < nblocks) ? g_bsum[tid] : 0;
    s[tid] = v;
    __syncthreads();
#pragma unroll
    for (int off = 1; off < 256; off <<= 1) {
        int t = (tid >= off) ? s[tid - off] : 0;
        __syncthreads();
        s[tid] += t;
        __syncthreads();
    }
    g_bsum[tid] = s[tid] - v;
}

__global__ void k_scan3(int n) {
    int i = blockIdx.x * blockDim.x + threadIdx.x;
    if (i < n) {
        int rp = g_rowptr[i] + g_bsum[blockIdx.x];
        g_rowptr[i] = rp;
        g_cursor[i] = rp;
    }
    if (i == 0) g_rowptr[Nn] = Ee;
}

__global__ void k_fill(const void* __restrict__ ei, int e_total) {
    int e = blockIdx.x * blockDim.x + threadIdx.x;
    if (e < e_total) {
        int mode = g_mode;
        int src = read_idx(ei, (size_t)e, mode);
        int dst = read_idx(ei, (size_t)Ee + e, mode);
        if ((unsigned)src < (unsigned)Nn && (unsigned)dst < (unsigned)Nn) {
            int pos = atomicAdd(&g_cursor[dst], 1);
            float nrm = g_dis[src] * g_dis[dst];
            g_edge[pos] = make_int2(src, __float_as_int(nrm));
        }
    }
}

// ---------------- GEMM1: g_raw = relu(x @ W1^T + b1), fused layer-0 att -----
// 64 rows x 128 cols per block; per-thread 8 rows x 4 cols as 4x4 f32x2 accs
// (rows paired in the 64-bit lanes).
__global__ void __launch_bounds__(256) k_gemm1(const float* __restrict__ x,
                                               const float* __restrict__ W1,
                                               const float* __restrict__ b1,
                                               const float* __restrict__ attl,
                                               const float* __restrict__ attr) {
    __shared__ float xs[32][72];    // xs[kk][row]
    __shared__ float ws[32][132];   // ws[kk][col]
    int tid = threadIdx.x;
    int lane = tid & 31;
    int rowBlk = blockIdx.x * 64;

    unsigned long long acc[4][4];   // [rowpair][col]; lo=row 2p, hi=row 2p+1
#pragma unroll
    for (int p = 0; p < 4; p++)
#pragma unroll
        for (int c = 0; c < 4; c++) acc[p][c] = 0ULL;

    for (int k0 = 0; k0 < Fdim; k0 += 32) {
#pragma unroll
        for (int u = 0; u < 2; u++) {
            int idx = tid + u * 256;
            int r = idx >> 3, c4 = idx & 7;
            float4 v = make_float4(0.f, 0.f, 0.f, 0.f);
            int gr = rowBlk + r;
            if (gr < Nn) v = *(const float4*)(x + (size_t)gr * Fdim + k0 + c4 * 4);
            xs[c4 * 4 + 0][r] = v.x; xs[c4 * 4 + 1][r] = v.y;
            xs[c4 * 4 + 2][r] = v.z; xs[c4 * 4 + 3][r] = v.w;
        }
#pragma unroll
        for (int u = 0; u < 4; u++) {
            int idx = tid + u * 256;
            int j = idx >> 3, c4 = idx & 7;
            float4 v = *(const float4*)(W1 + (size_t)j * Fdim + k0 + c4 * 4);
            ws[c4 * 4 + 0][j] = v.x; ws[c4 * 4 + 1][j] = v.y;
            ws[c4 * 4 + 2][j] = v.z; ws[c4 * 4 + 3][j] = v.w;
        }
        __syncthreads();

        int r0 = (tid >> 5) * 8;
        int c0 = lane * 4;
#pragma unroll
        for (int kk = 0; kk < 32; kk++) {
            float4 wv = *(const float4*)&ws[kk][c0];
            unsigned long long wd0 = dup2(wv.x), wd1 = dup2(wv.y);
            unsigned long long wd2 = dup2(wv.z), wd3 = dup2(wv.w);
            union { float4 f; unsigned long long u[2]; } ua, ub;
            ua.f = *(const float4*)&xs[kk][r0];
            ub.f = *(const float4*)&xs[kk][r0 + 4];
            unsigned long long xp[4] = {ua.u[0], ua.u[1], ub.u[0], ub.u[1]};
#pragma unroll
            for (int p = 0; p < 4; p++) {
                ffma2(acc[p][0], xp[p], wd0);
                ffma2(acc[p][1], xp[p], wd1);
                ffma2(acc[p][2], xp[p], wd2);
                ffma2(acc[p][3], xp[p], wd3);
            }
        }
        __syncthreads();
    }

    int r0 = (tid >> 5) * 8;
    int c0 = lane * 4;
    float bb0 = b1[c0], bb1 = b1[c0 + 1], bb2 = b1[c0 + 2], bb3 = b1[c0 + 3];
    float4 Lv = ((const float4*)attl)[lane];
    float4 Rv = ((const float4*)attr)[lane];

#pragma unroll
    for (int p = 0; p < 4; p++) {
        float2 c0v = unpk(acc[p][0]), c1v = unpk(acc[p][1]);
        float2 c2v = unpk(acc[p][2]), c3v = unpk(acc[p][3]);
#pragma unroll
        for (int half = 0; half < 2; half++) {
            int gr = rowBlk + r0 + 2 * p + half;
            float4 o;
            o.x = fmaxf((half ? c0v.y : c0v.x) + bb0, 0.f);
            o.y = fmaxf((half ? c1v.y : c1v.x) + bb1, 0.f);
            o.z = fmaxf((half ? c2v.y : c2v.x) + bb2, 0.f);
            o.w = fmaxf((half ? c3v.y : c3v.x) + bb3, 0.f);
            float pa = o.x * Lv.x + o.y * Lv.y + o.z * Lv.z + o.w * Lv.w;
            float pr = o.x * Rv.x + o.y * Rv.y + o.z * Rv.z + o.w * Rv.w;
#pragma unroll
            for (int off = 16; off; off >>= 1) {
                pa += __shfl_xor_sync(0xffffffffu, pa, off);
                pr += __shfl_xor_sync(0xffffffffu, pr, off);
            }
            if (gr < Nn) {
                *(float4*)(g_raw + (size_t)gr * Hdim + c0) = o;
                if (lane == 0) { g_al[0][gr] = pa; g_ar[0][gr] = pr; }
            }
        }
    }
}

// ---------------- aggregation: warp per node, CSR gather, fused next-att ----
__global__ void k_agg(int hin_sel, int hout_sel, int rd, int wr,
                      const float* __restrict__ attl_next,
                      const float* __restrict__ attr_next, int write_att) {
    int gw = (blockIdx.x * blockDim.x + threadIdx.x) >> 5;
    int lane = threadIdx.x & 31;
    if (gw >= Nn) return;
    const float4* hin4 = (const float4*)buf_sel(hin_sel);
    const float* alr = g_al[rd];

    float4 acc = make_float4(0.f, 0.f, 0.f, 0.f);
    float ar_i = g_ar[rd][gw];
    int start = g_rowptr[gw];
    int end = g_rowptr[gw + 1];

    for (int base = start; base < end; base += 32) {
        int e = base + lane;
        float coef = 0.f;
        int src = 0;
        if (e < end) {
            int2 ed = g_edge[e];
            src = ed.x;
            coef = tanhf(alr[src] + ar_i) * __int_as_float(ed.y);
        }
        int m = min(32, end - base);
        for (int j = 0; j < m; j++) {
            int s = __shfl_sync(0xffffffffu, src, j);
            float c = __shfl_sync(0xffffffffu, coef, j);
            float4 hv = hin4[(size_t)s * 32 + lane];
            acc.x = fmaf(c, hv.x, acc.x);
            acc.y = fmaf(c, hv.y, acc.y);
            acc.z = fmaf(c, hv.z, acc.z);
            acc.w = fmaf(c, hv.w, acc.w);
        }
    }
    float d = g_dis[gw];
    float cs = tanhf(alr[gw] + ar_i) * d * d;
    float4 hvi = hin4[(size_t)gw * 32 + lane];
    float4 rw = ((const float4*)g_raw)[(size_t)gw * 32 + lane];
    acc.x += cs * hvi.x + EPSv * rw.x;
    acc.y += cs * hvi.y + EPSv * rw.y;
    acc.z += cs * hvi.z + EPSv * rw.z;
    acc.w += cs * hvi.w + EPSv * rw.w;
    ((float4*)buf_sel(hout_sel))[(size_t)gw * 32 + lane] = acc;

    if (write_att) {
        float4 Lv = ((const float4*)attl_next)[lane];
        float4 Rv = ((const float4*)attr_next)[lane];
        float pa = acc.x * Lv.x + acc.y * Lv.y + acc.z * Lv.z + acc.w * Lv.w;
        float pr = acc.x * Rv.x + acc.y * Rv.y + acc.z * Rv.z + acc.w * Rv.w;
#pragma unroll
        for (int off = 16; off; off >>= 1) {
            pa += __shfl_xor_sync(0xffffffffu, pa, off);
            pr += __shfl_xor_sync(0xffffffffu, pr, off);
        }
        if (lane == 0) { g_al[wr][gw] = pa; g_ar[wr][gw] = pr; }
    }
}

// ---------------- output: logits + log_softmax ------------------------------
__global__ void k_out(int hin_sel, const float* __restrict__ W2,
                      const float* __restrict__ b2, float* __restrict__ out) {
    __shared__ float slog[8][40];
    int gw = (blockIdx.x * blockDim.x + threadIdx.x) >> 5;
    int lane = threadIdx.x & 31;
    int lw = threadIdx.x >> 5;
    if (gw >= Nn) return;
    const float4* h4 = (const float4*)(buf_sel(hin_sel) + (size_t)gw * Hdim);
    float4 hv = h4[lane];
#pragma unroll
    for (int c = 0; c < Cdim; c++) {
        float4 wv = *(const float4*)(W2 + (size_t)c * Hdim + lane * 4);
        float p = hv.x * wv.x + hv.y * wv.y + hv.z * wv.z + hv.w * wv.w;
        p += __shfl_down_sync(0xffffffffu, p, 16);
        p += __shfl_down_sync(0xffffffffu, p, 8);
        p += __shfl_down_sync(0xffffffffu, p, 4);
        p += __shfl_down_sync(0xffffffffu, p, 2);
        p += __shfl_down_sync(0xffffffffu, p, 1);
        if (lane == 0) slog[lw][c] = p + b2[c];
    }
    __syncwarp();
    float m = -1e30f;
    for (int c = lane; c < Cdim; c += 32) m = fmaxf(m, slog[lw][c]);
#pragma unroll
    for (int o = 16; o; o >>= 1) m = fmaxf(m, __shfl_xor_sync(0xffffffffu, m, o));
    float s = 0.f;
    for (int c = lane; c < Cdim; c += 32) s += expf(slog[lw][c] - m);
#pragma unroll
    for (int o = 16; o; o >>= 1) s += __shfl_xor_sync(0xffffffffu, s, o);
    float lse = m + logf(s);
    for (int c = lane; c < Cdim; c += 32)
        out[(size_t)gw * Cdim + c] = slog[lw][c] - lse;
}

// ---------------- launch -----------------------------------------------------
extern "C" void kernel_launch(void* const* d_in, const int* in_sizes, int n_in,
                              void* d_out, int out_size) {
    const float* x = (const float*)d_in[0];
    const void* ei = (const void*)d_in[1];
    const float* W1 = (const float*)d_in[2];
    const float* b1 = (const float*)d_in[3];
    const float* W2 = (const float*)d_in[4];
    const float* b2 = (const float*)d_in[5];
    const float* attl = (const float*)d_in[6];
    const float* attr = (const float*)d_in[7];
    float* out = (float*)d_out;

    const int NBn = (Nn + 255) / 256;        // 196
    const int NBe = (Ee + 255) / 256;        // 6250
    const int NBw = (Nn * 32 + 255) / 256;   // 6250 (warp per node)

    k_detect<<<1, 32>>>((const unsigned*)ei);
    k_zero_cnt<<<NBn, 256>>>(Nn);
    k_hist<<<NBe, 256>>>(ei, Ee);
    k_dis<<<NBn, 256>>>(Nn);
    k_scan1<<<NBn, 256>>>(Nn);
    k_scan2<<<1, 256>>>(NBn);
    k_scan3<<<NBn, 256>>>(Nn);
    k_fill<<<NBe, 256>>>(ei, Ee);

    k_gemm1<<<(Nn + 63) / 64, 256>>>(x, W1, b1, attl, attr);

    int sel_in = 0, sel_out = 1;
    for (int l = 0; l < 4; l++) {
        int rd = l & 1;
        int wr = 1 - rd;
        const float* al_n = (l < 3) ? attl + (l + 1) * Hdim : attl;
        const float* ar_n = (l < 3) ? attr + (l + 1) * Hdim : attr;
        k_agg<<<NBw, 256>>>(sel_in, sel_out, rd, wr, al_n, ar_n, l < 3 ? 1 : 0);
        sel_in = sel_out;
        sel_out = (sel_in == 1) ? 2 : 1;
    }
    k_out<<<NBw, 256>>>(sel_in, W2, b2, out);
}

// round 5
// speedup vs baseline: 1.0407x; 1.0153x over previous
#include <cuda_runtime.h>
#include <cuda_fp16.h>
#include <math.h>

#define Nn 50000
#define Ee 1600000
#define Fdim 512
#define Hdim 128
#define Cdim 40
#define EPSv 0.3f

// ---------------- scratch (static device globals; no allocations) ----------
__device__ __align__(16) float g_raw[(size_t)Nn * Hdim];
__device__ __align__(16) float g_hA[(size_t)Nn * Hdim];
__device__ __align__(16) float g_hB[(size_t)Nn * Hdim];
__device__ __align__(16) __half2 g_h16A[(size_t)Nn * (Hdim / 2)];
__device__ __align__(16) __half2 g_h16B[(size_t)Nn * (Hdim / 2)];
__device__ float g_al[2][Nn];
__device__ float g_ar[2][Nn];
__device__ float g_dis[Nn];
__device__ int   g_cnt[Nn];
__device__ int   g_rowptr[Nn + 1];
__device__ int   g_cursor[Nn];
__device__ __align__(16) int2 g_edge[Ee];
__device__ int   g_bsum[256];
__device__ int   g_mode;

__device__ __forceinline__ float* buf_sel(int s) {
    return s == 0 ? g_raw : (s == 1 ? g_hA : g_hB);
}
__device__ __forceinline__ __half2* h16_sel(int s) {
    return s == 0 ? g_h16A : g_h16B;
}

// ---------------- f32x2 helpers ---------------------------------------------
__device__ __forceinline__ void ffma2(unsigned long long& d,
                                      unsigned long long a,
                                      unsigned long long b) {
    asm volatile("fma.rn.f32x2 %0, %1, %2, %0;" : "+l"(d) : "l"(a), "l"(b));
}
__device__ __forceinline__ unsigned long long dup2(float w) {
    unsigned long long r;
    asm("mov.b64 %0, {%1,%1};" : "=l"(r) : "f"(w));
    return r;
}
__device__ __forceinline__ float2 unpk(unsigned long long v) {
    float2 r;
    asm("mov.b64 {%0,%1}, %2;" : "=f"(r.x), "=f"(r.y) : "l"(v));
    return r;
}

// ---------------- edge dtype detection -------------------------------------
__global__ void k_detect(const unsigned* __restrict__ w) {
    if (threadIdx.x != 0 || blockIdx.x != 0) return;
    int odd_zero = 0, big_exp = 0;
#pragma unroll
    for (int i = 0; i < 64; i++) {
        unsigned lo = w[2 * i];
        unsigned hi = w[2 * i + 1];
        if (hi == 0u) odd_zero++;
        if (lo >= 0x46000000u) big_exp++;
    }
    int m;
    if (odd_zero >= 60) m = 1;
    else if (big_exp >= 20) m = 2;
    else m = 0;
    g_mode = m;
}

__device__ __forceinline__ int read_idx(const void* ei, size_t pos, int mode) {
    if (mode == 1) return (int)((const long long*)ei)[pos];
    if (mode == 2) return (int)((const float*)ei)[pos];
    return ((const int*)ei)[pos];
}

// ---------------- CSR build --------------------------------------------------
__global__ void k_zero_cnt(int n) {
    int i = blockIdx.x * blockDim.x + threadIdx.x;
    if (i < n) g_cnt[i] = 0;
}

__global__ void k_hist(const void* __restrict__ ei, int e_total) {
    int e = blockIdx.x * blockDim.x + threadIdx.x;
    if (e < e_total) {
        int dst = read_idx(ei, (size_t)Ee + e, g_mode);
        if ((unsigned)dst < (unsigned)Nn) atomicAdd(&g_cnt[dst], 1);
    }
}

__global__ void k_dis(int n) {
    int i = blockIdx.x * blockDim.x + threadIdx.x;
    if (i < n) g_dis[i] = rsqrtf((float)(g_cnt[i] + 1));
}

__global__ void k_scan1(int n) {
    __shared__ int s[256];
    int tid = threadIdx.x;
    int i = blockIdx.x * 256 + tid;
    int v = (i < n) ? g_cnt[i] : 0;
    s[tid] = v;
    __syncthreads();
#pragma unroll
    for (int off = 1; off < 256; off <<= 1) {
        int t = (tid >= off) ? s[tid - off] : 0;
        __syncthreads();
        s[tid] += t;
        __syncthreads();
    }
    if (i < n) g_rowptr[i] = s[tid] - v;
    if (tid == 255) g_bsum[blockIdx.x] = s[255];
}

__global__ void k_scan2(int nblocks) {
    __shared__ int s[256];
    int tid = threadIdx.x;
    int v = (tid < nblocks) ? g_bsum[tid] : 0;
    s[tid] = v;
    __syncthreads();
#pragma unroll
    for (int off = 1; off < 256; off <<= 1) {
        int t = (tid >= off) ? s[tid - off] : 0;
        __syncthreads();
        s[tid] += t;
        __syncthreads();
    }
    g_bsum[tid] = s[tid] - v;
}

__global__ void k_scan3(int n) {
    int i = blockIdx.x * blockDim.x + threadIdx.x;
    if (i < n) {
        int rp = g_rowptr[i] + g_bsum[blockIdx.x];
        g_rowptr[i] = rp;
        g_cursor[i] = rp;
    }
    if (i == 0) g_rowptr[Nn] = Ee;
}

__global__ void k_fill(const void* __restrict__ ei, int e_total) {
    int e = blockIdx.x * blockDim.x + threadIdx.x;
    if (e < e_total) {
        int mode = g_mode;
        int src = read_idx(ei, (size_t)e, mode);
        int dst = read_idx(ei, (size_t)Ee + e, mode);
        if ((unsigned)src < (unsigned)Nn && (unsigned)dst < (unsigned)Nn) {
            int pos = atomicAdd(&g_cursor[dst], 1);
            float nrm = g_dis[src] * g_dis[dst];
            g_edge[pos] = make_int2(src, __float_as_int(nrm));
        }
    }
}

// ---------------- GEMM1: 128x128 tile, 8x8/thread, f32x2, fused att0 --------
__global__ void __launch_bounds__(256) k_gemm1(const float* __restrict__ x,
                                               const float* __restrict__ W1,
                                               const float* __restrict__ b1,
                                               const float* __restrict__ attl,
                                               const float* __restrict__ attr) {
    __shared__ float xs[32][132];   // xs[kk][row], 128 rows
    __shared__ float ws[32][132];   // ws[kk][col], 128 cols
    int tid = threadIdx.x;
    int rowBlk = blockIdx.x * 128;

    unsigned long long acc[4][8];   // [rowpair][col]
#pragma unroll
    for (int p = 0; p < 4; p++)
#pragma unroll
        for (int c = 0; c < 8; c++) acc[p][c] = 0ULL;

    int r0 = (tid >> 4) * 8;        // 0..120
    int c0 = (tid & 15) * 8;        // 0..120

    for (int k0 = 0; k0 < Fdim; k0 += 32) {
#pragma unroll
        for (int u = 0; u < 4; u++) {
            int idx = tid + u * 256;
            int r = idx >> 3, c4 = idx & 7;
            float4 v = make_float4(0.f, 0.f, 0.f, 0.f);
            int gr = rowBlk + r;
            if (gr < Nn) v = *(const float4*)(x + (size_t)gr * Fdim + k0 + c4 * 4);
            xs[c4 * 4 + 0][r] = v.x; xs[c4 * 4 + 1][r] = v.y;
            xs[c4 * 4 + 2][r] = v.z; xs[c4 * 4 + 3][r] = v.w;
        }
#pragma unroll
        for (int u = 0; u < 4; u++) {
            int idx = tid + u * 256;
            int j = idx >> 3, c4 = idx & 7;
            float4 v = *(const float4*)(W1 + (size_t)j * Fdim + k0 + c4 * 4);
            ws[c4 * 4 + 0][j] = v.x; ws[c4 * 4 + 1][j] = v.y;
            ws[c4 * 4 + 2][j] = v.z; ws[c4 * 4 + 3][j] = v.w;
        }
        __syncthreads();

#pragma unroll
        for (int kk = 0; kk < 32; kk++) {
            float4 wv0 = *(const float4*)&ws[kk][c0];
            float4 wv1 = *(const float4*)&ws[kk][c0 + 4];
            unsigned long long wd[8] = {dup2(wv0.x), dup2(wv0.y), dup2(wv0.z),
                                        dup2(wv0.w), dup2(wv1.x), dup2(wv1.y),
                                        dup2(wv1.z), dup2(wv1.w)};
            union { float4 f; unsigned long long u[2]; } ua, ub;
            ua.f = *(const float4*)&xs[kk][r0];
            ub.f = *(const float4*)&xs[kk][r0 + 4];
            unsigned long long xp[4] = {ua.u[0], ua.u[1], ub.u[0], ub.u[1]};
#pragma unroll
            for (int p = 0; p < 4; p++)
#pragma unroll
                for (int c = 0; c < 8; c++) ffma2(acc[p][c], xp[p], wd[c]);
        }
        __syncthreads();
    }

    float4 bl0 = *(const float4*)(b1 + c0);
    float4 bl1 = *(const float4*)(b1 + c0 + 4);
    float bb[8] = {bl0.x, bl0.y, bl0.z, bl0.w, bl1.x, bl1.y, bl1.z, bl1.w};
    float4 Ll0 = *(const float4*)(attl + c0);
    float4 Ll1 = *(const float4*)(attl + c0 + 4);
    float Lv[8] = {Ll0.x, Ll0.y, Ll0.z, Ll0.w, Ll1.x, Ll1.y, Ll1.z, Ll1.w};
    float4 Rr0 = *(const float4*)(attr + c0);
    float4 Rr1 = *(const float4*)(attr + c0 + 4);
    float Rv[8] = {Rr0.x, Rr0.y, Rr0.z, Rr0.w, Rr1.x, Rr1.y, Rr1.z, Rr1.w};

#pragma unroll
    for (int p = 0; p < 4; p++) {
        float2 cv[8];
#pragma unroll
        for (int c = 0; c < 8; c++) cv[c] = unpk(acc[p][c]);
#pragma unroll
        for (int half = 0; half < 2; half++) {
            int gr = rowBlk + r0 + 2 * p + half;
            float o[8];
#pragma unroll
            for (int c = 0; c < 8; c++)
                o[c] = fmaxf((half ? cv[c].y : cv[c].x) + bb[c], 0.f);
            float pa = 0.f, pr = 0.f;
#pragma unroll
            for (int c = 0; c < 8; c++) { pa += o[c] * Lv[c]; pr += o[c] * Rv[c]; }
#pragma unroll
            for (int off = 8; off; off >>= 1) {
                pa += __shfl_xor_sync(0xffffffffu, pa, off);
                pr += __shfl_xor_sync(0xffffffffu, pr, off);
            }
            if (gr < Nn) {
                *(float4*)(g_raw + (size_t)gr * Hdim + c0) =
                    make_float4(o[0], o[1], o[2], o[3]);
                *(float4*)(g_raw + (size_t)gr * Hdim + c0 + 4) =
                    make_float4(o[4], o[5], o[6], o[7]);
                __half2 hh[4];
#pragma unroll
                for (int q = 0; q < 4; q++)
                    hh[q] = __floats2half2_rn(o[2 * q], o[2 * q + 1]);
                *(uint4*)(g_h16A + (size_t)gr * 64 + (c0 >> 1)) = *(uint4*)hh;
                if ((tid & 15) == 0) { g_al[0][gr] = pa; g_ar[0][gr] = pr; }
            }
        }
    }
}

// ---------------- aggregation: warp/node, fp16 gather, fused next-att -------
__global__ void k_agg(int hin_sel, int hout_sel, int h16in_sel, int h16out_sel,
                      int rd, int wr, const float* __restrict__ attl_next,
                      const float* __restrict__ attr_next, int write_att,
                      int write_h16) {
    int gw = (blockIdx.x * blockDim.x + threadIdx.x) >> 5;
    int lane = threadIdx.x & 31;
    if (gw >= Nn) return;
    const float4* hin4 = (const float4*)buf_sel(hin_sel);
    const uint2* h16v = (const uint2*)h16_sel(h16in_sel);
    const float* alr = g_al[rd];

    float4 acc = make_float4(0.f, 0.f, 0.f, 0.f);
    float ar_i = g_ar[rd][gw];
    int start = g_rowptr[gw];
    int end = g_rowptr[gw + 1];

#define AGG_EDGE(J)                                                        \
    {                                                                      \
        int s = __shfl_sync(0xffffffffu, src, (J));                        \
        float c = __shfl_sync(0xffffffffu, coef, (J));                     \
        uint2 hv = h16v[(size_t)s * 32 + lane];                            \
        float2 f0 = __half22float2(*(__half2*)&hv.x);                      \
        float2 f1 = __half22float2(*(__half2*)&hv.y);                      \
        acc.x = fmaf(c, f0.x, acc.x); acc.y = fmaf(c, f0.y, acc.y);        \
        acc.z = fmaf(c, f1.x, acc.z); acc.w = fmaf(c, f1.y, acc.w);        \
    }

    for (int base = start; base < end; base += 32) {
        int rem = end - base;
        if (rem >= 32) {
            int2 ed = g_edge[base + lane];
            int src = ed.x;
            float coef = tanhf(alr[src] + ar_i) * __int_as_float(ed.y);
#pragma unroll 8
            for (int j = 0; j < 32; j++) AGG_EDGE(j)
        } else {
            float coef = 0.f;
            int src = 0;
            if (lane < rem) {
                int2 ed = g_edge[base + lane];
                src = ed.x;
                coef = tanhf(alr[src] + ar_i) * __int_as_float(ed.y);
            }
            for (int j = 0; j < rem; j++) AGG_EDGE(j)
        }
    }
#undef AGG_EDGE

    float d = g_dis[gw];
    float cs = tanhf(alr[gw] + ar_i) * d * d;
    float4 hvi = hin4[(size_t)gw * 32 + lane];
    float4 rw = ((const float4*)g_raw)[(size_t)gw * 32 + lane];
    acc.x += cs * hvi.x + EPSv * rw.x;
    acc.y += cs * hvi.y + EPSv * rw.y;
    acc.z += cs * hvi.z + EPSv * rw.z;
    acc.w += cs * hvi.w + EPSv * rw.w;
    ((float4*)buf_sel(hout_sel))[(size_t)gw * 32 + lane] = acc;

    if (write_h16) {
        __half2 hh[2];
        hh[0] = __floats2half2_rn(acc.x, acc.y);
        hh[1] = __floats2half2_rn(acc.z, acc.w);
        ((uint2*)h16_sel(h16out_sel))[(size_t)gw * 32 + lane] = *(uint2*)hh;
    }

    if (write_att) {
        float4 Lv = ((const float4*)attl_next)[lane];
        float4 Rv = ((const float4*)attr_next)[lane];
        float pa = acc.x * Lv.x + acc.y * Lv.y + acc.z * Lv.z + acc.w * Lv.w;
        float pr = acc.x * Rv.x + acc.y * Rv.y + acc.z * Rv.z + acc.w * Rv.w;
#pragma unroll
        for (int off = 16; off; off >>= 1) {
            pa += __shfl_xor_sync(0xffffffffu, pa, off);
            pr += __shfl_xor_sync(0xffffffffu, pr, off);
        }
        if (lane == 0) { g_al[wr][gw] = pa; g_ar[wr][gw] = pr; }
    }
}

// ---------------- output: logits + log_softmax ------------------------------
__global__ void k_out(int hin_sel, const float* __restrict__ W2,
                      const float* __restrict__ b2, float* __restrict__ out) {
    __shared__ float slog[8][40];
    int gw = (blockIdx.x * blockDim.x + threadIdx.x) >> 5;
    int lane = threadIdx.x & 31;
    int lw = threadIdx.x >> 5;
    if (gw >= Nn) return;
    const float4* h4 = (const float4*)(buf_sel(hin_sel) + (size_t)gw * Hdim);
    float4 hv = h4[lane];
#pragma unroll
    for (int c = 0; c < Cdim; c++) {
        float4 wv = *(const float4*)(W2 + (size_t)c * Hdim + lane * 4);
        float p = hv.x * wv.x + hv.y * wv.y + hv.z * wv.z + hv.w * wv.w;
        p += __shfl_down_sync(0xffffffffu, p, 16);
        p += __shfl_down_sync(0xffffffffu, p, 8);
        p += __shfl_down_sync(0xffffffffu, p, 4);
        p += __shfl_down_sync(0xffffffffu, p, 2);
        p += __shfl_down_sync(0xffffffffu, p, 1);
        if (lane == 0) slog[lw][c] = p + b2[c];
    }
    __syncwarp();
    float m = -1e30f;
    for (int c = lane; c < Cdim; c += 32) m = fmaxf(m, slog[lw][c]);
#pragma unroll
    for (int o = 16; o; o >>= 1) m = fmaxf(m, __shfl_xor_sync(0xffffffffu, m, o));
    float s = 0.f;
    for (int c = lane; c < Cdim; c += 32) s += expf(slog[lw][c] - m);
#pragma unroll
    for (int o = 16; o; o >>= 1) s += __shfl_xor_sync(0xffffffffu, s, o);
    float lse = m + logf(s);
    for (int c = lane; c < Cdim; c += 32)
        out[(size_t)gw * Cdim + c] = slog[lw][c] - lse;
}

// ---------------- launch -----------------------------------------------------
extern "C" void kernel_launch(void* const* d_in, const int* in_sizes, int n_in,
                              void* d_out, int out_size) {
    const float* x = (const float*)d_in[0];
    const void* ei = (const void*)d_in[1];
    const float* W1 = (const float*)d_in[2];
    const float* b1 = (const float*)d_in[3];
    const float* W2 = (const float*)d_in[4];
    const float* b2 = (const float*)d_in[5];
    const float* attl = (const float*)d_in[6];
    const float* attr = (const float*)d_in[7];
    float* out = (float*)d_out;

    const int NBn = (Nn + 255) / 256;
    const int NBe = (Ee + 255) / 256;
    const int NBw = (Nn * 32 + 255) / 256;

    k_detect<<<1, 32>>>((const unsigned*)ei);
    k_zero_cnt<<<NBn, 256>>>(Nn);
    k_hist<<<NBe, 256>>>(ei, Ee);
    k_dis<<<NBn, 256>>>(Nn);
    k_scan1<<<NBn, 256>>>(Nn);
    k_scan2<<<1, 256>>>(NBn);
    k_scan3<<<NBn, 256>>>(Nn);
    k_fill<<<NBe, 256>>>(ei, Ee);

    k_gemm1<<<(Nn + 127) / 128, 256>>>(x, W1, b1, attl, attr);

    int sel_in = 0, sel_out = 1;
    for (int l = 0; l < 4; l++) {
        int rd = l & 1;
        int wr = 1 - rd;
        int h16in = l & 1;
        int h16out = 1 - h16in;
        const float* al_n = (l < 3) ? attl + (l + 1) * Hdim : attl;
        const float* ar_n = (l < 3) ? attr + (l + 1) * Hdim : attr;
        k_agg<<<NBw, 256>>>(sel_in, sel_out, h16in, h16out, rd, wr,
                            al_n, ar_n, l < 3 ? 1 : 0, l < 3 ? 1 : 0);
        sel_in = sel_out;
        sel_out = (sel_in == 1) ? 2 : 1;
    }
    k_out<<<NBw, 256>>>(sel_in, W2, b2, out);
}